// round 2
// baseline (speedup 1.0000x reference)
#include <cuda_runtime.h>

#define NN 50000
#define NE 800000
#define NET 850000   // NE + NN self-loops
#define HEADS 4
#define HID 64
#define HC 256       // HEADS*HID
#define NT 200000
#define NEG 0.2f
#define EPSN 1e-5f

// ---------------- scratch (static device globals; no runtime alloc) -------
__device__ float    g_h[NN * HC];        // per-layer transformed features [N,H,C]
__device__ float    g_acc[NN * HC];      // attention-weighted accumulator
__device__ float    g_e[NET * HEADS];    // per-edge logits, then exp values
__device__ unsigned g_m[NN * HEADS];     // encoded scatter-max
__device__ float    g_s[NN * HEADS];     // scatter-sum of exp
__device__ float    g_es[NN * HEADS];    // (h*a_src).sum(-1)
__device__ float    g_ed[NN * HEADS];    // (h*a_dst).sum(-1)
__device__ float    g_pre[NN * HID];     // pre-GraphNorm features
__device__ float    g_x2[NN * HID];      // layer output (layer2 in / final emb)
__device__ float    g_stats[256];        // [sum(64) | sumsq(64) | mu*s(64) | inv(64)]

// monotone float<->uint encoding for atomicMax over floats (incl. negatives)
__device__ __forceinline__ unsigned fenc(float f) {
    unsigned u = __float_as_uint(f);
    return (u & 0x80000000u) ? ~u : (u | 0x80000000u);
}
__device__ __forceinline__ float fdec(unsigned u) {
    return __uint_as_float((u & 0x80000000u) ? (u & 0x7FFFFFFFu) : ~u);
}

// ---------------- kernels -------------------------------------------------
__global__ void k_zero() {
    int i = blockIdx.x * blockDim.x + threadIdx.x;
    int stride = gridDim.x * blockDim.x;
    for (int j = i; j < NN * HC; j += stride) g_acc[j] = 0.f;
    for (int j = i; j < NN * HEADS; j += stride) { g_m[j] = 0u; g_s[j] = 0.f; }
    if (i < 256) g_stats[i] = 0.f;
}

// h = x @ W1  (x: [N,128], W: [128,256] row-major). 8 nodes / 256-thread block.
__global__ void k_gemm1(const float* __restrict__ x, const float* __restrict__ W) {
    const int IN = 128;
    __shared__ float xs[8 * IN];
    int nb = blockIdx.x * 8;
    int t = threadIdx.x;
    for (int i = t; i < 8 * IN; i += 256) {
        int n = nb + i / IN;
        xs[i] = (n < NN) ? x[n * IN + (i % IN)] : 0.f;
    }
    __syncthreads();
    float acc[8] = {};
#pragma unroll 4
    for (int k = 0; k < IN; k++) {
        float wv = W[k * HC + t];
#pragma unroll
        for (int r = 0; r < 8; r++) acc[r] += xs[r * IN + k] * wv;
    }
#pragma unroll
    for (int r = 0; r < 8; r++) {
        int n = nb + r;
        if (n < NN) g_h[n * HC + t] = acc[r];
    }
}

// h = g_x2 @ W2 (g_x2: [N,64]). Reads the device-global directly.
__global__ void k_gemm2(const float* __restrict__ W) {
    const int IN = 64;
    __shared__ float xs[8 * IN];
    int nb = blockIdx.x * 8;
    int t = threadIdx.x;
    for (int i = t; i < 8 * IN; i += 256) {
        int n = nb + i / IN;
        xs[i] = (n < NN) ? g_x2[n * IN + (i % IN)] : 0.f;
    }
    __syncthreads();
    float acc[8] = {};
#pragma unroll 4
    for (int k = 0; k < IN; k++) {
        float wv = W[k * HC + t];
#pragma unroll
        for (int r = 0; r < 8; r++) acc[r] += xs[r * IN + k] * wv;
    }
#pragma unroll
    for (int r = 0; r < 8; r++) {
        int n = nb + r;
        if (n < NN) g_h[n * HC + t] = acc[r];
    }
}

// per-(node,head) attention projections; 1 block = 1 node, 4 warps = 4 heads
__global__ void k_scores(const float* __restrict__ a_src, const float* __restrict__ a_dst) {
    int n = blockIdx.x;
    int w = threadIdx.x >> 5, l = threadIdx.x & 31;
    const float* hp = &g_h[n * HC + w * HID];
    float h0 = hp[l], h1 = hp[l + 32];
    float vs = h0 * a_src[w * HID + l] + h1 * a_src[w * HID + l + 32];
    float vd = h0 * a_dst[w * HID + l] + h1 * a_dst[w * HID + l + 32];
#pragma unroll
    for (int o = 16; o > 0; o >>= 1) {
        vs += __shfl_xor_sync(~0u, vs, o);
        vd += __shfl_xor_sync(~0u, vd, o);
    }
    if (l == 0) { g_es[n * HEADS + w] = vs; g_ed[n * HEADS + w] = vd; }
}

__global__ void k_edge_max(const int* __restrict__ ei) {
    int gid = blockIdx.x * blockDim.x + threadIdx.x;
    if (gid >= NET * HEADS) return;
    int e = gid >> 2, h = gid & 3;
    int src = e < NE ? ei[e] : e - NE;
    int dst = e < NE ? ei[NE + e] : e - NE;
    float v = g_es[src * HEADS + h] + g_ed[dst * HEADS + h];
    v = v > 0.f ? v : NEG * v;               // leaky_relu
    g_e[gid] = v;
    atomicMax(&g_m[dst * HEADS + h], fenc(v));
}

__global__ void k_edge_exp(const int* __restrict__ ei) {
    int gid = blockIdx.x * blockDim.x + threadIdx.x;
    if (gid >= NET * HEADS) return;
    int e = gid >> 2, h = gid & 3;
    int dst = e < NE ? ei[NE + e] : e - NE;
    float p = __expf(g_e[gid] - fdec(g_m[dst * HEADS + h]));
    g_e[gid] = p;
    atomicAdd(&g_s[dst * HEADS + h], p);
}

// one warp per edge: acc[dst, h, :] += h[src, h, :] * alpha[h]
__global__ void k_edge_aggr(const int* __restrict__ ei) {
    int warp = (blockIdx.x * blockDim.x + threadIdx.x) >> 5;
    int l = threadIdx.x & 31;
    if (warp >= NET) return;
    int src = warp < NE ? ei[warp] : warp - NE;
    int dst = warp < NE ? ei[NE + warp] : warp - NE;
    float alpha[4];
#pragma unroll
    for (int h = 0; h < 4; h++)
        alpha[h] = g_e[warp * 4 + h] / (g_s[dst * 4 + h] + 1e-16f);
    const float* hs = &g_h[src * HC];
    float* ac = &g_acc[dst * HC];
#pragma unroll
    for (int j8 = 0; j8 < 8; j8++) {
        int j = j8 * 32 + l;
        atomicAdd(&ac[j], hs[j] * alpha[j8 >> 1]);
    }
}

// head-mean + bias -> g_pre; block-reduced column sum / sumsq for GraphNorm
__global__ void k_pre(const float* __restrict__ b) {
    int c = threadIdx.x & 63;
    int r = threadIdx.x >> 6;          // 4 node-rows in flight
    int base = blockIdx.x * 64;
    float bsum = 0.f, bsq = 0.f;
    for (int i = 0; i < 16; i++) {
        int n = base + i * 4 + r;
        if (n < NN) {
            const float* a = &g_acc[n * HC];
            float v = 0.25f * (a[c] + a[64 + c] + a[128 + c] + a[192 + c]) + b[c];
            g_pre[n * HID + c] = v;
            bsum += v; bsq += v * v;
        }
    }
    __shared__ float ssum[256], ssq[256];
    ssum[threadIdx.x] = bsum; ssq[threadIdx.x] = bsq;
    __syncthreads();
    if (r == 0) {
        float s = ssum[c] + ssum[64 + c] + ssum[128 + c] + ssum[192 + c];
        float q = ssq[c] + ssq[64 + c] + ssq[128 + c] + ssq[192 + c];
        atomicAdd(&g_stats[c], s);
        atomicAdd(&g_stats[64 + c], q);
    }
}

__global__ void k_gnstats(const float* __restrict__ gs) {
    int c = threadIdx.x;  // 64 threads
    float mu = g_stats[c] * (1.f / NN);
    float m2 = g_stats[64 + c] * (1.f / NN);
    float sc = gs[c];
    float var = m2 - 2.f * sc * mu * mu + sc * sc * mu * mu;
    g_stats[128 + c] = mu * sc;
    g_stats[192 + c] = rsqrtf(var + EPSN);
}

// GraphNorm affine + ReLU, writes the device-global g_x2 directly
__global__ void k_norm(const float* __restrict__ w, const float* __restrict__ bb) {
    int i = blockIdx.x * blockDim.x + threadIdx.x;
    if (i >= NN * HID) return;
    int c = i & 63;
    float v = (g_pre[i] - g_stats[128 + c]) * g_stats[192 + c] * w[c] + bb[c];
    g_x2[i] = v > 0.f ? v : 0.f;
}

// one warp per triplet: gather 4x64, layernorm(256), dot with fc_w
__global__ void k_trip(const int* __restrict__ trip, const float* __restrict__ lw,
                       const float* __restrict__ lb, const float* __restrict__ fw,
                       const float* __restrict__ fb, float* __restrict__ out) {
    int warp = (blockIdx.x * blockDim.x + threadIdx.x) >> 5;
    int l = threadIdx.x & 31;
    if (warp >= NT) return;
    int nodes[4];
#pragma unroll
    for (int q = 0; q < 4; q++) nodes[q] = trip[warp * 4 + q];
    float v[8];
    float sum = 0.f;
#pragma unroll
    for (int j8 = 0; j8 < 8; j8++) {
        int j = j8 * 32 + l;
        v[j8] = g_x2[nodes[j8 >> 1] * HID + (j & 63)];
        sum += v[j8];
    }
#pragma unroll
    for (int o = 16; o > 0; o >>= 1) sum += __shfl_xor_sync(~0u, sum, o);
    float mu = sum * (1.f / 256.f);
    float sq = 0.f;
#pragma unroll
    for (int j8 = 0; j8 < 8; j8++) { float d = v[j8] - mu; sq += d * d; }
#pragma unroll
    for (int o = 16; o > 0; o >>= 1) sq += __shfl_xor_sync(~0u, sq, o);
    float inv = rsqrtf(sq * (1.f / 256.f) + EPSN);
    float res = 0.f;
#pragma unroll
    for (int j8 = 0; j8 < 8; j8++) {
        int j = j8 * 32 + l;
        res += ((v[j8] - mu) * inv * lw[j] + lb[j]) * fw[j];
    }
#pragma unroll
    for (int o = 16; o > 0; o >>= 1) res += __shfl_xor_sync(~0u, res, o);
    if (l == 0) out[warp] = res + fb[0];
}

// ---------------- host ----------------------------------------------------
extern "C" void kernel_launch(void* const* d_in, const int* in_sizes, int n_in,
                              void* d_out, int out_size) {
    const float* x   = (const float*)d_in[0];
    // d_in[1] = edge_weight : unused by the reference computation
    const float* W1  = (const float*)d_in[2];
    const float* as1 = (const float*)d_in[3];
    const float* ad1 = (const float*)d_in[4];
    const float* b1  = (const float*)d_in[5];
    const float* W2  = (const float*)d_in[6];
    const float* as2 = (const float*)d_in[7];
    const float* ad2 = (const float*)d_in[8];
    const float* b2  = (const float*)d_in[9];
    const float* g1w = (const float*)d_in[10];
    const float* g1b = (const float*)d_in[11];
    const float* g1s = (const float*)d_in[12];
    const float* g2w = (const float*)d_in[13];
    const float* g2b = (const float*)d_in[14];
    const float* g2s = (const float*)d_in[15];
    const float* lnw = (const float*)d_in[16];
    const float* lnb = (const float*)d_in[17];
    const float* fcw = (const float*)d_in[18];
    const float* fcb = (const float*)d_in[19];
    const int*   ei  = (const int*)d_in[20];
    const int*   trp = (const int*)d_in[21];
    float* out = (float*)d_out;

    const int EH = NET * HEADS;

    // ---- layer 1 ----
    k_zero<<<512, 256>>>();
    k_gemm1<<<(NN + 7) / 8, 256>>>(x, W1);
    k_scores<<<NN, 128>>>(as1, ad1);
    k_edge_max<<<(EH + 255) / 256, 256>>>(ei);
    k_edge_exp<<<(EH + 255) / 256, 256>>>(ei);
    k_edge_aggr<<<(NET * 32 + 255) / 256, 256>>>(ei);
    k_pre<<<(NN + 63) / 64, 256>>>(b1);
    k_gnstats<<<1, 64>>>(g1s);
    k_norm<<<(NN * HID + 255) / 256, 256>>>(g1w, g1b);

    // ---- layer 2 ----
    k_zero<<<512, 256>>>();
    k_gemm2<<<(NN + 7) / 8, 256>>>(W2);
    k_scores<<<NN, 128>>>(as2, ad2);
    k_edge_max<<<(EH + 255) / 256, 256>>>(ei);
    k_edge_exp<<<(EH + 255) / 256, 256>>>(ei);
    k_edge_aggr<<<(NET * 32 + 255) / 256, 256>>>(ei);
    k_pre<<<(NN + 63) / 64, 256>>>(b2);
    k_gnstats<<<1, 64>>>(g2s);
    k_norm<<<(NN * HID + 255) / 256, 256>>>(g2w, g2b);

    // ---- triplet head ----
    k_trip<<<(NT * 32 + 255) / 256, 256>>>(trp, lnw, lnb, fcw, fcb, out);
}

// round 3
// speedup vs baseline: 2.0017x; 2.0017x over previous
#include <cuda_runtime.h>

#define NN 50000
#define NE 800000
#define NET 850000   // NE + NN self-loops
#define HEADS 4
#define HID 64
#define HC 256       // HEADS*HID
#define NT 200000
#define NEG 0.2f
#define EPSN 1e-5f
#define SCAN_CHUNK 512
#define SCAN_BLKS 98          // ceil((NN+1)/512)

// ---------------- scratch (static device globals; no runtime alloc) -------
__device__ float    g_h[NN * HC];        // transformed features [N,H,C]
__device__ float    g_e[NET * HEADS];    // per-sorted-edge exp values
__device__ float    g_es[NN * HEADS];    // (h*a_src).sum(-1)
__device__ float    g_ed[NN * HEADS];    // (h*a_dst).sum(-1)
__device__ float    g_pre[NN * HID];     // pre-GraphNorm features
__device__ float    g_x2[NN * HID];      // layer output
__device__ float    g_stats[256];        // [sum(64)|sumsq(64)|mu*s(64)|inv(64)]
__device__ int      g_row[NN + 1];       // CSR row offsets (by dst)
__device__ int      g_cur[NN];           // scatter cursors
__device__ int      g_csrc[NET];         // src node per dst-sorted edge
__device__ int      g_bsum[SCAN_BLKS];   // scan block sums

// ---------------- CSR build ------------------------------------------------
__global__ void k_rz() {
    int i = blockIdx.x * blockDim.x + threadIdx.x;
    int stride = gridDim.x * blockDim.x;
    for (int j = i; j <= NN; j += stride) g_row[j] = 0;
    if (i < 256) g_stats[i] = 0.f;
}

__global__ void k_hist(const int* __restrict__ ei) {
    int e = blockIdx.x * blockDim.x + threadIdx.x;
    if (e >= NET) return;
    int dst = e < NE ? ei[NE + e] : e - NE;
    atomicAdd(&g_row[dst + 1], 1);
}

__global__ void k_scan1() {
    __shared__ int sh[SCAN_CHUNK];
    int t = threadIdx.x;
    int idx = blockIdx.x * SCAN_CHUNK + t;
    sh[t] = (idx <= NN) ? g_row[idx] : 0;
    __syncthreads();
    for (int o = 1; o < SCAN_CHUNK; o <<= 1) {
        int x = (t >= o) ? sh[t - o] : 0;
        __syncthreads();
        sh[t] += x;
        __syncthreads();
    }
    if (idx <= NN) g_row[idx] = sh[t];
    if (t == SCAN_CHUNK - 1) g_bsum[blockIdx.x] = sh[t];
}

__global__ void k_scan2() {
    int run = 0;
    for (int i = 0; i < SCAN_BLKS; i++) {
        int v = g_bsum[i];
        g_bsum[i] = run;
        run += v;
    }
}

__global__ void k_scan3() {
    int t = threadIdx.x;
    int idx = blockIdx.x * SCAN_CHUNK + t;
    if (idx <= NN) {
        int v = g_row[idx] + g_bsum[blockIdx.x];
        g_row[idx] = v;
        if (idx < NN) g_cur[idx] = v;
    }
}

__global__ void k_scatter(const int* __restrict__ ei) {
    int e = blockIdx.x * blockDim.x + threadIdx.x;
    if (e >= NET) return;
    int src = e < NE ? ei[e] : e - NE;
    int dst = e < NE ? ei[NE + e] : e - NE;
    int pos = atomicAdd(&g_cur[dst], 1);
    g_csrc[pos] = src;
}

__global__ void k_zstats() {
    g_stats[threadIdx.x] = 0.f;   // 128 threads: sum + sumsq slots
}

// ---------------- GEMMs ----------------------------------------------------
// h = x @ W  (W: [IN,256] row-major). 16 node-rows per 256-thread block.
template <int IN>
__global__ void k_gemm(const float* __restrict__ x, const float* __restrict__ W) {
    __shared__ float xs[16 * IN];
    int nb = blockIdx.x * 16;
    int t = threadIdx.x;
    for (int i = t; i < 16 * IN; i += 256) {
        int n = nb + i / IN;
        xs[i] = (n < NN) ? x[n * IN + (i % IN)] : 0.f;
    }
    __syncthreads();
    float acc[16] = {};
#pragma unroll 4
    for (int k = 0; k < IN; k++) {
        float wv = W[k * HC + t];
#pragma unroll
        for (int r = 0; r < 16; r++) acc[r] += xs[r * IN + k] * wv;
    }
#pragma unroll
    for (int r = 0; r < 16; r++) {
        int n = nb + r;
        if (n < NN) g_h[n * HC + t] = acc[r];
    }
}

__global__ void k_gemm2w(const float* __restrict__ W) {
    const int IN = 64;
    __shared__ float xs[16 * IN];
    int nb = blockIdx.x * 16;
    int t = threadIdx.x;
    for (int i = t; i < 16 * IN; i += 256) {
        int n = nb + i / IN;
        xs[i] = (n < NN) ? g_x2[n * IN + (i % IN)] : 0.f;
    }
    __syncthreads();
    float acc[16] = {};
#pragma unroll 4
    for (int k = 0; k < IN; k++) {
        float wv = W[k * HC + t];
#pragma unroll
        for (int r = 0; r < 16; r++) acc[r] += xs[r * IN + k] * wv;
    }
#pragma unroll
    for (int r = 0; r < 16; r++) {
        int n = nb + r;
        if (n < NN) g_h[n * HC + t] = acc[r];
    }
}

// per-(node,head) attention projections; 1 block = 1 node, 4 warps = 4 heads
__global__ void k_scores(const float* __restrict__ a_src, const float* __restrict__ a_dst) {
    int n = blockIdx.x;
    int w = threadIdx.x >> 5, l = threadIdx.x & 31;
    const float* hp = &g_h[n * HC + w * HID];
    float h0 = hp[l], h1 = hp[l + 32];
    float vs = h0 * a_src[w * HID + l] + h1 * a_src[w * HID + l + 32];
    float vd = h0 * a_dst[w * HID + l] + h1 * a_dst[w * HID + l + 32];
#pragma unroll
    for (int o = 16; o > 0; o >>= 1) {
        vs += __shfl_xor_sync(~0u, vs, o);
        vd += __shfl_xor_sync(~0u, vd, o);
    }
    if (l == 0) { g_es[n * HEADS + w] = vs; g_ed[n * HEADS + w] = vd; }
}

// ---------------- fused GAT edge pipeline: one warp per dst node -----------
// leaky -> segmax -> exp/sum -> alpha-weighted aggr -> head-mean + bias
// plus block-reduced GraphNorm stats. No feature atomics.
__global__ void k_gat(const float* __restrict__ b) {
    int t = threadIdx.x, w = t >> 5, l = t & 31;
    int v = blockIdx.x * 8 + w;
    float p0 = 0.f, p1 = 0.f;
    if (v < NN) {
        int beg = g_row[v], end = g_row[v + 1];
        float ed0 = g_ed[v * 4 + 0], ed1 = g_ed[v * 4 + 1];
        float ed2 = g_ed[v * 4 + 2], ed3 = g_ed[v * 4 + 3];
        // pass A: segment max per head (lane-strided)
        float m0 = -1e30f, m1 = -1e30f, m2 = -1e30f, m3 = -1e30f;
        for (int i = beg + l; i < end; i += 32) {
            int s = g_csrc[i];
            float e0 = g_es[s * 4 + 0] + ed0; e0 = e0 > 0.f ? e0 : NEG * e0;
            float e1 = g_es[s * 4 + 1] + ed1; e1 = e1 > 0.f ? e1 : NEG * e1;
            float e2 = g_es[s * 4 + 2] + ed2; e2 = e2 > 0.f ? e2 : NEG * e2;
            float e3 = g_es[s * 4 + 3] + ed3; e3 = e3 > 0.f ? e3 : NEG * e3;
            m0 = fmaxf(m0, e0); m1 = fmaxf(m1, e1);
            m2 = fmaxf(m2, e2); m3 = fmaxf(m3, e3);
        }
#pragma unroll
        for (int o = 16; o > 0; o >>= 1) {
            m0 = fmaxf(m0, __shfl_xor_sync(~0u, m0, o));
            m1 = fmaxf(m1, __shfl_xor_sync(~0u, m1, o));
            m2 = fmaxf(m2, __shfl_xor_sync(~0u, m2, o));
            m3 = fmaxf(m3, __shfl_xor_sync(~0u, m3, o));
        }
        // pass B: exp + sum, store exp to g_e
        float s0 = 0.f, s1 = 0.f, s2 = 0.f, s3 = 0.f;
        for (int i = beg + l; i < end; i += 32) {
            int s = g_csrc[i];
            float e0 = g_es[s * 4 + 0] + ed0; e0 = e0 > 0.f ? e0 : NEG * e0;
            float e1 = g_es[s * 4 + 1] + ed1; e1 = e1 > 0.f ? e1 : NEG * e1;
            float e2 = g_es[s * 4 + 2] + ed2; e2 = e2 > 0.f ? e2 : NEG * e2;
            float e3 = g_es[s * 4 + 3] + ed3; e3 = e3 > 0.f ? e3 : NEG * e3;
            float q0 = __expf(e0 - m0), q1 = __expf(e1 - m1);
            float q2 = __expf(e2 - m2), q3 = __expf(e3 - m3);
            g_e[i * 4 + 0] = q0; g_e[i * 4 + 1] = q1;
            g_e[i * 4 + 2] = q2; g_e[i * 4 + 3] = q3;
            s0 += q0; s1 += q1; s2 += q2; s3 += q3;
        }
#pragma unroll
        for (int o = 16; o > 0; o >>= 1) {
            s0 += __shfl_xor_sync(~0u, s0, o);
            s1 += __shfl_xor_sync(~0u, s1, o);
            s2 += __shfl_xor_sync(~0u, s2, o);
            s3 += __shfl_xor_sync(~0u, s3, o);
        }
        float i0 = 1.f / (s0 + 1e-16f), i1 = 1.f / (s1 + 1e-16f);
        float i2 = 1.f / (s2 + 1e-16f), i3 = 1.f / (s3 + 1e-16f);
        // pass C: sequential edges, lanes across features
        float acc[8] = {};
#pragma unroll 2
        for (int i = beg; i < end; i++) {
            int s = g_csrc[i];                      // broadcast
            float a0 = g_e[i * 4 + 0] * i0;
            float a1 = g_e[i * 4 + 1] * i1;
            float a2 = g_e[i * 4 + 2] * i2;
            float a3 = g_e[i * 4 + 3] * i3;
            const float* hp = &g_h[s * HC + l];
            acc[0] += hp[0]   * a0; acc[1] += hp[32]  * a0;
            acc[2] += hp[64]  * a1; acc[3] += hp[96]  * a1;
            acc[4] += hp[128] * a2; acc[5] += hp[160] * a2;
            acc[6] += hp[192] * a3; acc[7] += hp[224] * a3;
        }
        p0 = 0.25f * (acc[0] + acc[2] + acc[4] + acc[6]) + b[l];
        p1 = 0.25f * (acc[1] + acc[3] + acc[5] + acc[7]) + b[32 + l];
        g_pre[v * HID + l] = p0;
        g_pre[v * HID + 32 + l] = p1;
    }
    // GraphNorm stats: block-reduce over 8 warps, then 128 atomics per block
    __shared__ float ss0[256], sq0[256], ss1[256], sq1[256];
    ss0[t] = p0; sq0[t] = p0 * p0; ss1[t] = p1; sq1[t] = p1 * p1;
    __syncthreads();
    if (t < 32) {
        float a = 0.f, q = 0.f;
#pragma unroll
        for (int ww = 0; ww < 8; ww++) { a += ss0[ww * 32 + t]; q += sq0[ww * 32 + t]; }
        atomicAdd(&g_stats[t], a);
        atomicAdd(&g_stats[64 + t], q);
    } else if (t < 64) {
        int c = t - 32;
        float a = 0.f, q = 0.f;
#pragma unroll
        for (int ww = 0; ww < 8; ww++) { a += ss1[ww * 32 + c]; q += sq1[ww * 32 + c]; }
        atomicAdd(&g_stats[32 + c], a);
        atomicAdd(&g_stats[64 + 32 + c], q);
    }
}

__global__ void k_gnstats(const float* __restrict__ gs) {
    int c = threadIdx.x;  // 64 threads
    float mu = g_stats[c] * (1.f / NN);
    float m2 = g_stats[64 + c] * (1.f / NN);
    float sc = gs[c];
    float var = m2 - 2.f * sc * mu * mu + sc * sc * mu * mu;
    g_stats[128 + c] = mu * sc;
    g_stats[192 + c] = rsqrtf(var + EPSN);
}

__global__ void k_norm(const float* __restrict__ w, const float* __restrict__ bb) {
    int i = blockIdx.x * blockDim.x + threadIdx.x;
    if (i >= NN * HID) return;
    int c = i & 63;
    float v = (g_pre[i] - g_stats[128 + c]) * g_stats[192 + c] * w[c] + bb[c];
    g_x2[i] = v > 0.f ? v : 0.f;
}

// one warp per triplet: gather 4x64, layernorm(256), dot with fc_w
__global__ void k_trip(const int* __restrict__ trip, const float* __restrict__ lw,
                       const float* __restrict__ lb, const float* __restrict__ fw,
                       const float* __restrict__ fb, float* __restrict__ out) {
    int warp = (blockIdx.x * blockDim.x + threadIdx.x) >> 5;
    int l = threadIdx.x & 31;
    if (warp >= NT) return;
    int nodes[4];
#pragma unroll
    for (int q = 0; q < 4; q++) nodes[q] = trip[warp * 4 + q];
    float v[8];
    float sum = 0.f;
#pragma unroll
    for (int j8 = 0; j8 < 8; j8++) {
        int j = j8 * 32 + l;
        v[j8] = g_x2[nodes[j8 >> 1] * HID + (j & 63)];
        sum += v[j8];
    }
#pragma unroll
    for (int o = 16; o > 0; o >>= 1) sum += __shfl_xor_sync(~0u, sum, o);
    float mu = sum * (1.f / 256.f);
    float sq = 0.f;
#pragma unroll
    for (int j8 = 0; j8 < 8; j8++) { float d = v[j8] - mu; sq += d * d; }
#pragma unroll
    for (int o = 16; o > 0; o >>= 1) sq += __shfl_xor_sync(~0u, sq, o);
    float inv = rsqrtf(sq * (1.f / 256.f) + EPSN);
    float res = 0.f;
#pragma unroll
    for (int j8 = 0; j8 < 8; j8++) {
        int j = j8 * 32 + l;
        res += ((v[j8] - mu) * inv * lw[j] + lb[j]) * fw[j];
    }
#pragma unroll
    for (int o = 16; o > 0; o >>= 1) res += __shfl_xor_sync(~0u, res, o);
    if (l == 0) out[warp] = res + fb[0];
}

// ---------------- host ----------------------------------------------------
extern "C" void kernel_launch(void* const* d_in, const int* in_sizes, int n_in,
                              void* d_out, int out_size) {
    const float* x   = (const float*)d_in[0];
    // d_in[1] = edge_weight : unused by the reference computation
    const float* W1  = (const float*)d_in[2];
    const float* as1 = (const float*)d_in[3];
    const float* ad1 = (const float*)d_in[4];
    const float* b1  = (const float*)d_in[5];
    const float* W2  = (const float*)d_in[6];
    const float* as2 = (const float*)d_in[7];
    const float* ad2 = (const float*)d_in[8];
    const float* b2  = (const float*)d_in[9];
    const float* g1w = (const float*)d_in[10];
    const float* g1b = (const float*)d_in[11];
    const float* g1s = (const float*)d_in[12];
    const float* g2w = (const float*)d_in[13];
    const float* g2b = (const float*)d_in[14];
    const float* g2s = (const float*)d_in[15];
    const float* lnw = (const float*)d_in[16];
    const float* lnb = (const float*)d_in[17];
    const float* fcw = (const float*)d_in[18];
    const float* fcb = (const float*)d_in[19];
    const int*   ei  = (const int*)d_in[20];
    const int*   trp = (const int*)d_in[21];
    float* out = (float*)d_out;

    // ---- CSR build (shared by both layers) ----
    k_rz<<<128, 256>>>();
    k_hist<<<(NET + 255) / 256, 256>>>(ei);
    k_scan1<<<SCAN_BLKS, SCAN_CHUNK>>>();
    k_scan2<<<1, 1>>>();
    k_scan3<<<SCAN_BLKS, SCAN_CHUNK>>>();
    k_scatter<<<(NET + 255) / 256, 256>>>(ei);

    // ---- layer 1 ----
    k_gemm<128><<<(NN + 15) / 16, 256>>>(x, W1);
    k_scores<<<NN, 128>>>(as1, ad1);
    k_gat<<<(NN + 7) / 8, 256>>>(b1);
    k_gnstats<<<1, 64>>>(g1s);
    k_norm<<<(NN * HID + 255) / 256, 256>>>(g1w, g1b);

    // ---- layer 2 ----
    k_zstats<<<1, 128>>>();
    k_gemm2w<<<(NN + 15) / 16, 256>>>(W2);
    k_scores<<<NN, 128>>>(as2, ad2);
    k_gat<<<(NN + 7) / 8, 256>>>(b2);
    k_gnstats<<<1, 64>>>(g2s);
    k_norm<<<(NN * HID + 255) / 256, 256>>>(g2w, g2b);

    // ---- triplet head ----
    k_trip<<<(NT * 32 + 255) / 256, 256>>>(trp, lnw, lnb, fcw, fcb, out);
}

// round 4
// speedup vs baseline: 2.0947x; 1.0464x over previous
#include <cuda_runtime.h>
#include <cuda_fp16.h>

#define NN 50000
#define NE 800000
#define NET 850000   // NE + NN self-loops
#define HEADS 4
#define HID 64
#define HC 256       // HEADS*HID
#define NT 200000
#define NEG 0.2f
#define EPSN 1e-5f
#define SCAN_CHUNK 512
#define SCAN_BLKS 98          // ceil((NN+1)/512)

// ---------------- scratch (static device globals; no runtime alloc) -------
__device__ __half2  g_hh[NN * 128];      // transformed features, half2 [N][4 heads][32 pairs]
__device__ float4   g_e4[NET];           // per-sorted-edge logits -> exp values
__device__ float4   g_es4[NN];           // (h*a_src).sum(-1) per head
__device__ float4   g_ed4[NN];           // (h*a_dst).sum(-1) per head
__device__ float    g_pre[NN * HID];     // pre-GraphNorm features
__device__ float    g_x2[NN * HID];      // layer output
__device__ float    g_stats[256];        // [sum(64)|sumsq(64)|mu*s(64)|inv(64)]
__device__ float    g_wt[128 * 8];       // W projected through a_src/a_dst: [IN][8]
__device__ int      g_row[NN + 1];       // CSR row offsets (by dst)
__device__ int      g_cur[NN];           // scatter cursors
__device__ int      g_csrc[NET];         // src node per dst-sorted edge
__device__ int      g_bsum[SCAN_BLKS];   // scan block sums

// ---------------- CSR build ------------------------------------------------
__global__ void k_rz() {
    int i = blockIdx.x * blockDim.x + threadIdx.x;
    int stride = gridDim.x * blockDim.x;
    for (int j = i; j <= NN; j += stride) g_row[j] = 0;
    if (i < 256) g_stats[i] = 0.f;
}

__global__ void k_hist(const int* __restrict__ ei) {
    int e = blockIdx.x * blockDim.x + threadIdx.x;
    if (e >= NET) return;
    int dst = e < NE ? ei[NE + e] : e - NE;
    atomicAdd(&g_row[dst + 1], 1);
}

__global__ void k_scan1() {
    __shared__ int sh[SCAN_CHUNK];
    int t = threadIdx.x;
    int idx = blockIdx.x * SCAN_CHUNK + t;
    sh[t] = (idx <= NN) ? g_row[idx] : 0;
    __syncthreads();
    for (int o = 1; o < SCAN_CHUNK; o <<= 1) {
        int x = (t >= o) ? sh[t - o] : 0;
        __syncthreads();
        sh[t] += x;
        __syncthreads();
    }
    if (idx <= NN) g_row[idx] = sh[t];
    if (t == SCAN_CHUNK - 1) g_bsum[blockIdx.x] = sh[t];
}

__global__ void k_scan2() {
    int run = 0;
    for (int i = 0; i < SCAN_BLKS; i++) {
        int v = g_bsum[i];
        g_bsum[i] = run;
        run += v;
    }
}

__global__ void k_scan3() {
    int t = threadIdx.x;
    int idx = blockIdx.x * SCAN_CHUNK + t;
    if (idx <= NN) {
        int v = g_row[idx] + g_bsum[blockIdx.x];
        g_row[idx] = v;
        if (idx < NN) g_cur[idx] = v;
    }
}

__global__ void k_scatter(const int* __restrict__ ei) {
    int e = blockIdx.x * blockDim.x + threadIdx.x;
    if (e >= NET) return;
    int src = e < NE ? ei[e] : e - NE;
    int dst = e < NE ? ei[NE + e] : e - NE;
    int pos = atomicAdd(&g_cur[dst], 1);
    g_csrc[pos] = src;
}

__global__ void k_zstats() {
    g_stats[threadIdx.x] = 0.f;   // 128 threads: sum + sumsq slots
}

// ---------------- attention-vector projection: wt = W @ [a_src|a_dst] -----
// wt[k][2j+sd] = sum_c W[k][j*64+c] * a_{sd}[j*64+c]
__global__ void k_wt(const float* __restrict__ W, const float* __restrict__ as,
                     const float* __restrict__ ad, int IN) {
    int wid = (blockIdx.x * blockDim.x + threadIdx.x) >> 5;
    int l = threadIdx.x & 31;
    if (wid >= IN * 8) return;
    int k = wid >> 3, o = wid & 7, j = o >> 1;
    const float* a = (o & 1) ? ad : as;
    float v = W[k * HC + j * 64 + l] * a[j * 64 + l]
            + W[k * HC + j * 64 + 32 + l] * a[j * 64 + 32 + l];
#pragma unroll
    for (int off = 16; off; off >>= 1) v += __shfl_xor_sync(~0u, v, off);
    if (l == 0) g_wt[wid] = v;
}

// scores from the ORIGINAL fp32 input: e = x @ wt  (exact, no h needed)
template <int IN>
__device__ __forceinline__ void scores_body(const float* __restrict__ x) {
    int warp = (blockIdx.x * blockDim.x + threadIdx.x) >> 5;
    int l = threadIdx.x & 31;
    if (warp >= NN) return;
    float e[8] = {};
#pragma unroll
    for (int u = 0; u < IN / 32; u++) {
        int k = u * 32 + l;
        float xv = x[warp * IN + k];
        const float* wr = &g_wt[k * 8];
#pragma unroll
        for (int o = 0; o < 8; o++) e[o] += xv * wr[o];
    }
#pragma unroll
    for (int o = 0; o < 8; o++) {
#pragma unroll
        for (int off = 16; off; off >>= 1) e[o] += __shfl_xor_sync(~0u, e[o], off);
    }
    if (l == 0) {
        g_es4[warp] = make_float4(e[0], e[2], e[4], e[6]);
        g_ed4[warp] = make_float4(e[1], e[3], e[5], e[7]);
    }
}
__global__ void k_scores1(const float* __restrict__ x) { scores_body<128>(x); }
__global__ void k_scores2() { scores_body<64>(g_x2); }

// ---------------- GEMM: h = x @ W -> half2, 32 rows/block, 4col x 8row ----
template <int IN>
__device__ __forceinline__ void gemm_body(const float* __restrict__ x,
                                          const float* __restrict__ W) {
    __shared__ float2 xs[32 * IN / 2];
    int nb = blockIdx.x * 32;
    int t = threadIdx.x;
    int ct = t & 63, rg = t >> 6;
    {
        const int TOT = 32 * IN / 2;
        for (int i = t; i < TOT; i += 256) {
            int n = nb + i / (IN / 2);
            int k2 = i % (IN / 2);
            xs[i] = (n < NN) ? ((const float2*)x)[n * (IN / 2) + k2]
                             : make_float2(0.f, 0.f);
        }
    }
    __syncthreads();
    float acc[4][8] = {};
#pragma unroll 2
    for (int k2 = 0; k2 < IN / 2; k2++) {
        int k = k2 * 2;
        float wv0[4], wv1[4];
#pragma unroll
        for (int j = 0; j < 4; j++) {
            wv0[j] = W[k * HC + ct + 64 * j];
            wv1[j] = W[(k + 1) * HC + ct + 64 * j];
        }
#pragma unroll
        for (int i = 0; i < 8; i++) {
            float2 xv = xs[(rg * 8 + i) * (IN / 2) + k2];
#pragma unroll
            for (int j = 0; j < 4; j++)
                acc[j][i] += xv.x * wv0[j] + xv.y * wv1[j];
        }
    }
    // write half2: thread holds feature ct of head j; pair adjacent ct
#pragma unroll
    for (int i = 0; i < 8; i++) {
        int n = nb + rg * 8 + i;
#pragma unroll
        for (int j = 0; j < 4; j++) {
            float other = __shfl_xor_sync(~0u, acc[j][i], 1);
            if (!(ct & 1) && n < NN)
                g_hh[n * 128 + j * 32 + (ct >> 1)] = __floats2half2_rn(acc[j][i], other);
        }
    }
}
__global__ void k_gemm1(const float* __restrict__ x, const float* __restrict__ W) {
    gemm_body<128>(x, W);
}
__global__ void k_gemm2(const float* __restrict__ W) {
    gemm_body<64>(g_x2, W);
}

// ---------------- fused GAT edge pipeline: one warp per dst node -----------
__global__ void k_gat(const float* __restrict__ b) {
    int t = threadIdx.x, w = t >> 5, l = t & 31;
    int v = blockIdx.x * 8 + w;
    float p0 = 0.f, p1 = 0.f;
    if (v < NN) {
        int beg = g_row[v], end = g_row[v + 1];
        float4 ed = g_ed4[v];
        // pass A: logits + segment max
        float m0 = -1e30f, m1 = -1e30f, m2 = -1e30f, m3 = -1e30f;
        for (int i = beg + l; i < end; i += 32) {
            int s = g_csrc[i];
            float4 es = g_es4[s];
            float e0 = es.x + ed.x; e0 = e0 > 0.f ? e0 : NEG * e0;
            float e1 = es.y + ed.y; e1 = e1 > 0.f ? e1 : NEG * e1;
            float e2 = es.z + ed.z; e2 = e2 > 0.f ? e2 : NEG * e2;
            float e3 = es.w + ed.w; e3 = e3 > 0.f ? e3 : NEG * e3;
            g_e4[i] = make_float4(e0, e1, e2, e3);
            m0 = fmaxf(m0, e0); m1 = fmaxf(m1, e1);
            m2 = fmaxf(m2, e2); m3 = fmaxf(m3, e3);
        }
#pragma unroll
        for (int o = 16; o > 0; o >>= 1) {
            m0 = fmaxf(m0, __shfl_xor_sync(~0u, m0, o));
            m1 = fmaxf(m1, __shfl_xor_sync(~0u, m1, o));
            m2 = fmaxf(m2, __shfl_xor_sync(~0u, m2, o));
            m3 = fmaxf(m3, __shfl_xor_sync(~0u, m3, o));
        }
        // pass B: exp + sum (coalesced reload of logits)
        float s0 = 0.f, s1 = 0.f, s2 = 0.f, s3 = 0.f;
        for (int i = beg + l; i < end; i += 32) {
            float4 e = g_e4[i];
            e.x = __expf(e.x - m0); e.y = __expf(e.y - m1);
            e.z = __expf(e.z - m2); e.w = __expf(e.w - m3);
            g_e4[i] = e;
            s0 += e.x; s1 += e.y; s2 += e.z; s3 += e.w;
        }
#pragma unroll
        for (int o = 16; o > 0; o >>= 1) {
            s0 += __shfl_xor_sync(~0u, s0, o);
            s1 += __shfl_xor_sync(~0u, s1, o);
            s2 += __shfl_xor_sync(~0u, s2, o);
            s3 += __shfl_xor_sync(~0u, s3, o);
        }
        float i0 = 1.f / (s0 + 1e-16f), i1 = 1.f / (s1 + 1e-16f);
        float i2 = 1.f / (s2 + 1e-16f), i3 = 1.f / (s3 + 1e-16f);
        // pass C: sequential edges, lanes across feature pairs (half2)
        float2 a0 = {0.f, 0.f}, a1 = {0.f, 0.f}, a2 = {0.f, 0.f}, a3 = {0.f, 0.f};
#pragma unroll 2
        for (int i = beg; i < end; i++) {
            int s = g_csrc[i];                      // broadcast
            float4 q = g_e4[i];                     // broadcast
            float w0 = q.x * i0, w1 = q.y * i1, w2 = q.z * i2, w3 = q.w * i3;
            const __half2* hp = &g_hh[s * 128 + l];
            float2 f0 = __half22float2(hp[0]);
            float2 f1 = __half22float2(hp[32]);
            float2 f2 = __half22float2(hp[64]);
            float2 f3 = __half22float2(hp[96]);
            a0.x += f0.x * w0; a0.y += f0.y * w0;
            a1.x += f1.x * w1; a1.y += f1.y * w1;
            a2.x += f2.x * w2; a2.y += f2.y * w2;
            a3.x += f3.x * w3; a3.y += f3.y * w3;
        }
        p0 = 0.25f * (a0.x + a1.x + a2.x + a3.x) + b[2 * l];
        p1 = 0.25f * (a0.y + a1.y + a2.y + a3.y) + b[2 * l + 1];
        ((float2*)g_pre)[v * 32 + l] = make_float2(p0, p1);
    }
    // GraphNorm stats: block-reduce over 8 warps, then 128 atomics per block
    __shared__ float ss0[256], sq0[256], ss1[256], sq1[256];
    ss0[t] = p0; sq0[t] = p0 * p0; ss1[t] = p1; sq1[t] = p1 * p1;
    __syncthreads();
    if (t < 64) {
        int lane = t >> 1, sel = t & 1;
        const float* sv = sel ? ss1 : ss0;
        const float* qv = sel ? sq1 : sq0;
        float a = 0.f, q = 0.f;
#pragma unroll
        for (int ww = 0; ww < 8; ww++) { a += sv[ww * 32 + lane]; q += qv[ww * 32 + lane]; }
        atomicAdd(&g_stats[t], a);          // column t = 2*lane + sel
        atomicAdd(&g_stats[64 + t], q);
    }
}

__global__ void k_gnstats(const float* __restrict__ gs) {
    int c = threadIdx.x;  // 64 threads
    float mu = g_stats[c] * (1.f / NN);
    float m2 = g_stats[64 + c] * (1.f / NN);
    float sc = gs[c];
    float var = m2 - 2.f * sc * mu * mu + sc * sc * mu * mu;
    g_stats[128 + c] = mu * sc;
    g_stats[192 + c] = rsqrtf(var + EPSN);
}

__global__ void k_norm(const float* __restrict__ w, const float* __restrict__ bb) {
    int i = blockIdx.x * blockDim.x + threadIdx.x;
    if (i >= NN * HID) return;
    int c = i & 63;
    float v = (g_pre[i] - g_stats[128 + c]) * g_stats[192 + c] * w[c] + bb[c];
    g_x2[i] = v > 0.f ? v : 0.f;
}

// one warp per triplet: gather 4x64, layernorm(256), dot with fc_w
__global__ void k_trip(const int* __restrict__ trip, const float* __restrict__ lw,
                       const float* __restrict__ lb, const float* __restrict__ fw,
                       const float* __restrict__ fb, float* __restrict__ out) {
    int warp = (blockIdx.x * blockDim.x + threadIdx.x) >> 5;
    int l = threadIdx.x & 31;
    if (warp >= NT) return;
    int nodes[4];
#pragma unroll
    for (int q = 0; q < 4; q++) nodes[q] = trip[warp * 4 + q];
    float v[8];
    float sum = 0.f;
#pragma unroll
    for (int j8 = 0; j8 < 8; j8++) {
        int j = j8 * 32 + l;
        v[j8] = g_x2[nodes[j8 >> 1] * HID + (j & 63)];
        sum += v[j8];
    }
#pragma unroll
    for (int o = 16; o > 0; o >>= 1) sum += __shfl_xor_sync(~0u, sum, o);
    float mu = sum * (1.f / 256.f);
    float sq = 0.f;
#pragma unroll
    for (int j8 = 0; j8 < 8; j8++) { float d = v[j8] - mu; sq += d * d; }
#pragma unroll
    for (int o = 16; o > 0; o >>= 1) sq += __shfl_xor_sync(~0u, sq, o);
    float inv = rsqrtf(sq * (1.f / 256.f) + EPSN);
    float res = 0.f;
#pragma unroll
    for (int j8 = 0; j8 < 8; j8++) {
        int j = j8 * 32 + l;
        res += ((v[j8] - mu) * inv * lw[j] + lb[j]) * fw[j];
    }
#pragma unroll
    for (int o = 16; o > 0; o >>= 1) res += __shfl_xor_sync(~0u, res, o);
    if (l == 0) out[warp] = res + fb[0];
}

// ---------------- host ----------------------------------------------------
extern "C" void kernel_launch(void* const* d_in, const int* in_sizes, int n_in,
                              void* d_out, int out_size) {
    const float* x   = (const float*)d_in[0];
    // d_in[1] = edge_weight : unused by the reference computation
    const float* W1  = (const float*)d_in[2];
    const float* as1 = (const float*)d_in[3];
    const float* ad1 = (const float*)d_in[4];
    const float* b1  = (const float*)d_in[5];
    const float* W2  = (const float*)d_in[6];
    const float* as2 = (const float*)d_in[7];
    const float* ad2 = (const float*)d_in[8];
    const float* b2  = (const float*)d_in[9];
    const float* g1w = (const float*)d_in[10];
    const float* g1b = (const float*)d_in[11];
    const float* g1s = (const float*)d_in[12];
    const float* g2w = (const float*)d_in[13];
    const float* g2b = (const float*)d_in[14];
    const float* g2s = (const float*)d_in[15];
    const float* lnw = (const float*)d_in[16];
    const float* lnb = (const float*)d_in[17];
    const float* fcw = (const float*)d_in[18];
    const float* fcb = (const float*)d_in[19];
    const int*   ei  = (const int*)d_in[20];
    const int*   trp = (const int*)d_in[21];
    float* out = (float*)d_out;

    // ---- CSR build (shared by both layers) ----
    k_rz<<<128, 256>>>();
    k_hist<<<(NET + 255) / 256, 256>>>(ei);
    k_scan1<<<SCAN_BLKS, SCAN_CHUNK>>>();
    k_scan2<<<1, 1>>>();
    k_scan3<<<SCAN_BLKS, SCAN_CHUNK>>>();
    k_scatter<<<(NET + 255) / 256, 256>>>(ei);

    // ---- layer 1 ----
    k_wt<<<(128 * 8 * 32 + 255) / 256, 256>>>(W1, as1, ad1, 128);
    k_scores1<<<(NN * 32 + 255) / 256, 256>>>(x);
    k_gemm1<<<(NN + 31) / 32, 256>>>(x, W1);
    k_gat<<<(NN + 7) / 8, 256>>>(b1);
    k_gnstats<<<1, 64>>>(g1s);
    k_norm<<<(NN * HID + 255) / 256, 256>>>(g1w, g1b);

    // ---- layer 2 ----
    k_zstats<<<1, 128>>>();
    k_wt<<<(64 * 8 * 32 + 255) / 256, 256>>>(W2, as2, ad2, 64);
    k_scores2<<<(NN * 32 + 255) / 256, 256>>>();
    k_gemm2<<<(NN + 31) / 32, 256>>>(W2);
    k_gat<<<(NN + 7) / 8, 256>>>(b2);
    k_gnstats<<<1, 64>>>(g2s);
    k_norm<<<(NN * HID + 255) / 256, 256>>>(g2w, g2b);

    // ---- triplet head ----
    k_trip<<<(NT * 32 + 255) / 256, 256>>>(trp, lnw, lnb, fcw, fcb, out);
}

// round 5
// speedup vs baseline: 2.5683x; 1.2261x over previous
#include <cuda_runtime.h>
#include <cuda_fp16.h>

#define NN 50000
#define NE 800000
#define NET 850000   // NE + NN self-loops
#define HEADS 4
#define HID 64
#define HC 256       // HEADS*HID
#define NT 200000
#define NEG 0.2f
#define EPSN 1e-5f
#define SCAN_CHUNK 512
#define SCAN_BLKS 98          // ceil((NN+1)/512)

// ---------------- scratch (static device globals; no runtime alloc) -------
__device__ __half2  g_hh[NN * 128];      // transformed features, half2 [N][4 heads][32 pairs]
__device__ float4   g_es4[NN];           // (h*a_src).sum(-1) per head
__device__ float4   g_ed4[NN];           // (h*a_dst).sum(-1) per head
__device__ float    g_pre[NN * HID];     // pre-GraphNorm features
__device__ float    g_x2[NN * HID];      // layer output
__device__ float    g_stats[256];        // [L1: sum|sumsq (128)] [L2: sum|sumsq (128)]
__device__ float    g_wt[2 * 1024];      // W projected through a_src/a_dst: [layer][IN][8]
__device__ int      g_row[NN + 1];       // CSR row offsets (by dst)
__device__ int      g_cur[NN];           // scatter cursors
__device__ int      g_csrc[NET];         // src node per dst-sorted edge
__device__ int      g_bsum[SCAN_BLKS];   // scan block sums

// ---------------- CSR build ------------------------------------------------
__global__ void k_rz() {
    int i = blockIdx.x * blockDim.x + threadIdx.x;
    int stride = gridDim.x * blockDim.x;
    for (int j = i; j <= NN; j += stride) g_row[j] = 0;
    if (i < 256) g_stats[i] = 0.f;
}

__global__ void k_hist(const int* __restrict__ ei) {
    int e = blockIdx.x * blockDim.x + threadIdx.x;
    if (e >= NET) return;
    int dst = e < NE ? ei[NE + e] : e - NE;
    atomicAdd(&g_row[dst + 1], 1);
}

__global__ void k_scan1() {
    __shared__ int sh[SCAN_CHUNK];
    int t = threadIdx.x;
    int idx = blockIdx.x * SCAN_CHUNK + t;
    sh[t] = (idx <= NN) ? g_row[idx] : 0;
    __syncthreads();
    for (int o = 1; o < SCAN_CHUNK; o <<= 1) {
        int x = (t >= o) ? sh[t - o] : 0;
        __syncthreads();
        sh[t] += x;
        __syncthreads();
    }
    if (idx <= NN) g_row[idx] = sh[t];
    if (t == SCAN_CHUNK - 1) g_bsum[blockIdx.x] = sh[t];
}

// exclusive scan of the 98 block sums with one warp
__global__ void k_scan2() {
    int l = threadIdx.x;
    int carry = 0;
    for (int base = 0; base < SCAN_BLKS; base += 32) {
        int idx = base + l;
        int v = (idx < SCAN_BLKS) ? g_bsum[idx] : 0;
        int inc = v;
#pragma unroll
        for (int o = 1; o < 32; o <<= 1) {
            int u = __shfl_up_sync(~0u, inc, o);
            if (l >= o) inc += u;
        }
        if (idx < SCAN_BLKS) g_bsum[idx] = inc - v + carry;
        carry += __shfl_sync(~0u, inc, 31);
    }
}

__global__ void k_scan3() {
    int t = threadIdx.x;
    int idx = blockIdx.x * SCAN_CHUNK + t;
    if (idx <= NN) {
        int v = g_row[idx] + g_bsum[blockIdx.x];
        g_row[idx] = v;
        if (idx < NN) g_cur[idx] = v;
    }
}

__global__ void k_scatter(const int* __restrict__ ei) {
    int e = blockIdx.x * blockDim.x + threadIdx.x;
    if (e >= NET) return;
    int src = e < NE ? ei[e] : e - NE;
    int dst = e < NE ? ei[NE + e] : e - NE;
    int pos = atomicAdd(&g_cur[dst], 1);
    g_csrc[pos] = src;
}

// ---------------- attention-vector projection: wt = W @ [a_src|a_dst] -----
__global__ void k_wt(const float* __restrict__ W, const float* __restrict__ as,
                     const float* __restrict__ ad, int IN, int off) {
    int wid = (blockIdx.x * blockDim.x + threadIdx.x) >> 5;
    int l = threadIdx.x & 31;
    if (wid >= IN * 8) return;
    int k = wid >> 3, o = wid & 7, j = o >> 1;
    const float* a = (o & 1) ? ad : as;
    float v = W[k * HC + j * 64 + l] * a[j * 64 + l]
            + W[k * HC + j * 64 + 32 + l] * a[j * 64 + 32 + l];
#pragma unroll
    for (int s = 16; s; s >>= 1) v += __shfl_xor_sync(~0u, v, s);
    if (l == 0) g_wt[off + wid] = v;
}

// ---------------- GEMM (h = x@W -> half2) + fused attention scores --------
template <int IN>
__device__ __forceinline__ void gemm_body(const float* __restrict__ x,
                                          const float* __restrict__ W, int wtOff) {
    __shared__ float2 xs[32 * IN / 2];
    int nb = blockIdx.x * 32;
    int t = threadIdx.x;
    int ct = t & 63, rg = t >> 6;
    {
        const int TOT = 32 * IN / 2;
        for (int i = t; i < TOT; i += 256) {
            int n = nb + i / (IN / 2);
            int k2 = i % (IN / 2);
            xs[i] = (n < NN) ? ((const float2*)x)[n * (IN / 2) + k2]
                             : make_float2(0.f, 0.f);
        }
    }
    __syncthreads();
    float acc[4][8] = {};
#pragma unroll 2
    for (int k2 = 0; k2 < IN / 2; k2++) {
        int k = k2 * 2;
        float wv0[4], wv1[4];
#pragma unroll
        for (int j = 0; j < 4; j++) {
            wv0[j] = W[k * HC + ct + 64 * j];
            wv1[j] = W[(k + 1) * HC + ct + 64 * j];
        }
#pragma unroll
        for (int i = 0; i < 8; i++) {
            float2 xv = xs[(rg * 8 + i) * (IN / 2) + k2];
#pragma unroll
            for (int j = 0; j < 4; j++)
                acc[j][i] += xv.x * wv0[j] + xv.y * wv1[j];
        }
    }
    // write half2: thread holds feature ct of head j; pair adjacent ct
#pragma unroll
    for (int i = 0; i < 8; i++) {
        int n = nb + rg * 8 + i;
#pragma unroll
        for (int j = 0; j < 4; j++) {
            float other = __shfl_xor_sync(~0u, acc[j][i], 1);
            if (!(ct & 1) && n < NN)
                g_hh[n * 128 + j * 32 + (ct >> 1)] = __floats2half2_rn(acc[j][i], other);
        }
    }
    // fused scores: thread t -> (row r, output o); e = x_row . wt[:,o]  (exact fp32)
    {
        int r = t >> 3, o = t & 7;
        float e = 0.f;
#pragma unroll 4
        for (int k2 = 0; k2 < IN / 2; k2++) {
            float2 xv = xs[r * (IN / 2) + k2];
            e += xv.x * g_wt[wtOff + (2 * k2) * 8 + o]
               + xv.y * g_wt[wtOff + (2 * k2 + 1) * 8 + o];
        }
        int n = nb + r;
        if (n < NN) {
            if (o & 1) ((float*)g_ed4)[n * 4 + (o >> 1)] = e;
            else       ((float*)g_es4)[n * 4 + (o >> 1)] = e;
        }
    }
}
__global__ void k_gemm1(const float* __restrict__ x, const float* __restrict__ W) {
    gemm_body<128>(x, W, 0);
}
__global__ void k_gemm2(const float* __restrict__ W) {
    gemm_body<64>(g_x2, W, 1024);
}

// ---------------- single-pass fused GAT: one warp per dst node -------------
// unshifted softmax (logits are O(1); identical after normalization)
__global__ void k_gat(const float* __restrict__ b, int statsOff) {
    int t = threadIdx.x, w = t >> 5, l = t & 31;
    int v = blockIdx.x * 16 + w;
    float p0 = 0.f, p1 = 0.f;
    if (v < NN) {
        int beg = g_row[v], end = g_row[v + 1];
        float4 ed = g_ed4[v];
        float s0 = 0.f, s1 = 0.f, s2 = 0.f, s3 = 0.f;
        float2 a0 = {0.f, 0.f}, a1 = {0.f, 0.f}, a2 = {0.f, 0.f}, a3 = {0.f, 0.f};
#pragma unroll 2
        for (int i = beg; i < end; i++) {
            int s = g_csrc[i];                       // broadcast
            float4 es = g_es4[s];                    // broadcast
            float e0 = es.x + ed.x; e0 = e0 > 0.f ? e0 : NEG * e0;
            float e1 = es.y + ed.y; e1 = e1 > 0.f ? e1 : NEG * e1;
            float e2 = es.z + ed.z; e2 = e2 > 0.f ? e2 : NEG * e2;
            float e3 = es.w + ed.w; e3 = e3 > 0.f ? e3 : NEG * e3;
            float q0 = __expf(e0), q1 = __expf(e1);
            float q2 = __expf(e2), q3 = __expf(e3);
            s0 += q0; s1 += q1; s2 += q2; s3 += q3;
            const __half2* hp = &g_hh[s * 128 + l];
            float2 f0 = __half22float2(hp[0]);
            float2 f1 = __half22float2(hp[32]);
            float2 f2 = __half22float2(hp[64]);
            float2 f3 = __half22float2(hp[96]);
            a0.x += f0.x * q0; a0.y += f0.y * q0;
            a1.x += f1.x * q1; a1.y += f1.y * q1;
            a2.x += f2.x * q2; a2.y += f2.y * q2;
            a3.x += f3.x * q3; a3.y += f3.y * q3;
        }
        float i0 = 0.25f / s0, i1 = 0.25f / s1;
        float i2 = 0.25f / s2, i3 = 0.25f / s3;
        p0 = a0.x * i0 + a1.x * i1 + a2.x * i2 + a3.x * i3 + b[2 * l];
        p1 = a0.y * i0 + a1.y * i1 + a2.y * i2 + a3.y * i3 + b[2 * l + 1];
        ((float2*)g_pre)[v * 32 + l] = make_float2(p0, p1);
    }
    // GraphNorm stats: block-reduce over 16 warps, 128 atomics per block
    __shared__ float ss0[512], sq0[512], ss1[512], sq1[512];
    ss0[t] = p0; sq0[t] = p0 * p0; ss1[t] = p1; sq1[t] = p1 * p1;
    __syncthreads();
    if (t < 64) {
        int lane = t >> 1, sel = t & 1;
        const float* sv = sel ? ss1 : ss0;
        const float* qv = sel ? sq1 : sq0;
        float a = 0.f, q = 0.f;
#pragma unroll
        for (int ww = 0; ww < 16; ww++) { a += sv[ww * 32 + lane]; q += qv[ww * 32 + lane]; }
        atomicAdd(&g_stats[statsOff + t], a);        // feature t = 2*lane + sel
        atomicAdd(&g_stats[statsOff + 64 + t], q);
    }
}

// GraphNorm affine + ReLU, stats derived inline (no separate gnstats kernel)
__global__ void k_norm(const float* __restrict__ w, const float* __restrict__ bb,
                       const float* __restrict__ gs, int statsOff) {
    int i = blockIdx.x * blockDim.x + threadIdx.x;
    if (i >= NN * HID) return;
    int c = i & 63;
    float mu = g_stats[statsOff + c] * (1.f / NN);
    float m2 = g_stats[statsOff + 64 + c] * (1.f / NN);
    float sc = gs[c];
    float var = m2 - 2.f * sc * mu * mu + sc * sc * mu * mu;
    float v = (g_pre[i] - mu * sc) * rsqrtf(var + EPSN) * w[c] + bb[c];
    g_x2[i] = v > 0.f ? v : 0.f;
}

// one warp per triplet: gather 4x64, layernorm(256), dot with fc_w
__global__ void k_trip(const int* __restrict__ trip, const float* __restrict__ lw,
                       const float* __restrict__ lb, const float* __restrict__ fw,
                       const float* __restrict__ fb, float* __restrict__ out) {
    int warp = (blockIdx.x * blockDim.x + threadIdx.x) >> 5;
    int l = threadIdx.x & 31;
    if (warp >= NT) return;
    int nodes[4];
#pragma unroll
    for (int q = 0; q < 4; q++) nodes[q] = trip[warp * 4 + q];
    float v[8];
    float sum = 0.f;
#pragma unroll
    for (int j8 = 0; j8 < 8; j8++) {
        int j = j8 * 32 + l;
        v[j8] = g_x2[nodes[j8 >> 1] * HID + (j & 63)];
        sum += v[j8];
    }
#pragma unroll
    for (int o = 16; o > 0; o >>= 1) sum += __shfl_xor_sync(~0u, sum, o);
    float mu = sum * (1.f / 256.f);
    float sq = 0.f;
#pragma unroll
    for (int j8 = 0; j8 < 8; j8++) { float d = v[j8] - mu; sq += d * d; }
#pragma unroll
    for (int o = 16; o > 0; o >>= 1) sq += __shfl_xor_sync(~0u, sq, o);
    float inv = rsqrtf(sq * (1.f / 256.f) + EPSN);
    float res = 0.f;
#pragma unroll
    for (int j8 = 0; j8 < 8; j8++) {
        int j = j8 * 32 + l;
        res += ((v[j8] - mu) * inv * lw[j] + lb[j]) * fw[j];
    }
#pragma unroll
    for (int o = 16; o > 0; o >>= 1) res += __shfl_xor_sync(~0u, res, o);
    if (l == 0) out[warp] = res + fb[0];
}

// ---------------- host ----------------------------------------------------
extern "C" void kernel_launch(void* const* d_in, const int* in_sizes, int n_in,
                              void* d_out, int out_size) {
    const float* x   = (const float*)d_in[0];
    // d_in[1] = edge_weight : unused by the reference computation
    const float* W1  = (const float*)d_in[2];
    const float* as1 = (const float*)d_in[3];
    const float* ad1 = (const float*)d_in[4];
    const float* b1  = (const float*)d_in[5];
    const float* W2  = (const float*)d_in[6];
    const float* as2 = (const float*)d_in[7];
    const float* ad2 = (const float*)d_in[8];
    const float* b2  = (const float*)d_in[9];
    const float* g1w = (const float*)d_in[10];
    const float* g1b = (const float*)d_in[11];
    const float* g1s = (const float*)d_in[12];
    const float* g2w = (const float*)d_in[13];
    const float* g2b = (const float*)d_in[14];
    const float* g2s = (const float*)d_in[15];
    const float* lnw = (const float*)d_in[16];
    const float* lnb = (const float*)d_in[17];
    const float* fcw = (const float*)d_in[18];
    const float* fcb = (const float*)d_in[19];
    const int*   ei  = (const int*)d_in[20];
    const int*   trp = (const int*)d_in[21];
    float* out = (float*)d_out;

    // ---- CSR build + attention-vector projections ----
    k_rz<<<128, 256>>>();
    k_wt<<<128, 256>>>(W1, as1, ad1, 128, 0);
    k_wt<<<64, 256>>>(W2, as2, ad2, 64, 1024);
    k_hist<<<(NET + 255) / 256, 256>>>(ei);
    k_scan1<<<SCAN_BLKS, SCAN_CHUNK>>>();
    k_scan2<<<1, 32>>>();
    k_scan3<<<SCAN_BLKS, SCAN_CHUNK>>>();
    k_scatter<<<(NET + 255) / 256, 256>>>(ei);

    // ---- layer 1 ----
    k_gemm1<<<(NN + 31) / 32, 256>>>(x, W1);
    k_gat<<<(NN + 15) / 16, 512>>>(b1, 0);
    k_norm<<<(NN * HID + 255) / 256, 256>>>(g1w, g1b, g1s, 0);

    // ---- layer 2 ----
    k_gemm2<<<(NN + 31) / 32, 256>>>(W2);
    k_gat<<<(NN + 15) / 16, 512>>>(b2, 128);
    k_norm<<<(NN * HID + 255) / 256, 256>>>(g2w, g2b, g2s, 128);

    // ---- triplet head ----
    k_trip<<<(NT * 32 + 255) / 256, 256>>>(trp, lnw, lnb, fcw, fcb, out);
}

// round 6
// speedup vs baseline: 2.9045x; 1.1309x over previous
#include <cuda_runtime.h>
#include <cuda_fp16.h>

#define NN 50000
#define NE 800000
#define NET 850000   // NE + NN self-loops
#define HEADS 4
#define HID 64
#define HC 256       // HEADS*HID
#define NT 200000
#define NEG 0.2f
#define EPSN 1e-5f
#define SCAN_CHUNK 512
#define SCAN_BLKS 98          // ceil((NN+1)/512)

// ---------------- scratch (static device globals; no runtime alloc) -------
__device__ __half2  g_hh[NN * 128];      // transformed features, half2 [N][4 heads][32 pairs]
__device__ float4   g_es4[NN];           // (h*a_src).sum(-1) per head
__device__ float4   g_ed4[NN];           // (h*a_dst).sum(-1) per head
__device__ float    g_pre[NN * HID];     // pre-GraphNorm features
__device__ float    g_x2[NN * HID];      // layer output
__device__ float    g_stats[256];        // [L1: sum|sumsq (128)] [L2: sum|sumsq (128)]
__device__ float    g_wt[2 * 1024];      // W projected through a_src/a_dst: [layer][IN][8]
__device__ int      g_row[NN + 1];       // CSR row offsets (by dst)
__device__ int      g_cur[NN];           // scatter cursors
__device__ int      g_csrc[NET];         // src node per dst-sorted edge
__device__ int      g_bsum[SCAN_BLKS];   // scan block sums

// ---------------- CSR build ------------------------------------------------
__global__ void k_rz() {
    int i = blockIdx.x * blockDim.x + threadIdx.x;
    int stride = gridDim.x * blockDim.x;
    for (int j = i; j <= NN; j += stride) g_row[j] = 0;
    if (i < 256) g_stats[i] = 0.f;
}

__global__ void k_hist(const int* __restrict__ ei) {
    int e = blockIdx.x * blockDim.x + threadIdx.x;
    if (e >= NET) return;
    int dst = e < NE ? ei[NE + e] : e - NE;
    atomicAdd(&g_row[dst + 1], 1);
}

__global__ void k_scan1() {
    __shared__ int sh[SCAN_CHUNK];
    int t = threadIdx.x;
    int idx = blockIdx.x * SCAN_CHUNK + t;
    sh[t] = (idx <= NN) ? g_row[idx] : 0;
    __syncthreads();
    for (int o = 1; o < SCAN_CHUNK; o <<= 1) {
        int x = (t >= o) ? sh[t - o] : 0;
        __syncthreads();
        sh[t] += x;
        __syncthreads();
    }
    if (idx <= NN) g_row[idx] = sh[t];
    if (t == SCAN_CHUNK - 1) g_bsum[blockIdx.x] = sh[t];
}

// exclusive scan of the 98 block sums with one warp
__global__ void k_scan2() {
    int l = threadIdx.x;
    int carry = 0;
    for (int base = 0; base < SCAN_BLKS; base += 32) {
        int idx = base + l;
        int v = (idx < SCAN_BLKS) ? g_bsum[idx] : 0;
        int inc = v;
#pragma unroll
        for (int o = 1; o < 32; o <<= 1) {
            int u = __shfl_up_sync(~0u, inc, o);
            if (l >= o) inc += u;
        }
        if (idx < SCAN_BLKS) g_bsum[idx] = inc - v + carry;
        carry += __shfl_sync(~0u, inc, 31);
    }
}

__global__ void k_scan3() {
    int t = threadIdx.x;
    int idx = blockIdx.x * SCAN_CHUNK + t;
    if (idx <= NN) {
        int v = g_row[idx] + g_bsum[blockIdx.x];
        g_row[idx] = v;
        if (idx < NN) g_cur[idx] = v;
    }
}

__global__ void k_scatter(const int* __restrict__ ei) {
    int e = blockIdx.x * blockDim.x + threadIdx.x;
    if (e >= NET) return;
    int src = e < NE ? ei[e] : e - NE;
    int dst = e < NE ? ei[NE + e] : e - NE;
    int pos = atomicAdd(&g_cur[dst], 1);
    g_csrc[pos] = src;
}

// ---------------- attention-vector projection: wt = W @ [a_src|a_dst] -----
__global__ void k_wt(const float* __restrict__ W, const float* __restrict__ as,
                     const float* __restrict__ ad, int IN, int off) {
    int wid = (blockIdx.x * blockDim.x + threadIdx.x) >> 5;
    int l = threadIdx.x & 31;
    if (wid >= IN * 8) return;
    int k = wid >> 3, o = wid & 7, j = o >> 1;
    const float* a = (o & 1) ? ad : as;
    float v = W[k * HC + j * 64 + l] * a[j * 64 + l]
            + W[k * HC + j * 64 + 32 + l] * a[j * 64 + 32 + l];
#pragma unroll
    for (int s = 16; s; s >>= 1) v += __shfl_xor_sync(~0u, v, s);
    if (l == 0) g_wt[off + wid] = v;
}

// ---------------- GEMM (h = x@W -> half2) + fused attention scores --------
// 32 rows / block, 256 threads = 64 col-groups (4 contiguous cols) x 4 row-groups (8 rows)
// inner loop k4: 4x LDG.128 (W) + 8x LDS.128 (x) -> 128 FMA  => FFMA-bound
template <int IN>
__device__ __forceinline__ void gemm_body(const float* __restrict__ x,
                                          const float* __restrict__ W, int wtOff) {
    __shared__ float4 xs[32 * IN / 4];
    __shared__ float ws[IN * 8];
    int nb = blockIdx.x * 32;
    int t = threadIdx.x;
    int cg = t & 63, rg = t >> 6;
    {
        const int TOT = 32 * IN / 4;
        for (int i = t; i < TOT; i += 256) {
            int n = nb + i / (IN / 4);
            int k4 = i % (IN / 4);
            xs[i] = (n < NN) ? ((const float4*)x)[n * (IN / 4) + k4]
                             : make_float4(0.f, 0.f, 0.f, 0.f);
        }
        for (int i = t; i < IN * 8; i += 256) ws[i] = g_wt[wtOff + i];
    }
    __syncthreads();
    float4 acc[8];
#pragma unroll
    for (int i = 0; i < 8; i++) acc[i] = make_float4(0.f, 0.f, 0.f, 0.f);
#pragma unroll 2
    for (int k4 = 0; k4 < IN / 4; k4++) {
        float4 wv0 = ((const float4*)W)[(k4 * 4 + 0) * 64 + cg];
        float4 wv1 = ((const float4*)W)[(k4 * 4 + 1) * 64 + cg];
        float4 wv2 = ((const float4*)W)[(k4 * 4 + 2) * 64 + cg];
        float4 wv3 = ((const float4*)W)[(k4 * 4 + 3) * 64 + cg];
#pragma unroll
        for (int i = 0; i < 8; i++) {
            float4 xv = xs[(rg * 8 + i) * (IN / 4) + k4];
            acc[i].x += xv.x * wv0.x + xv.y * wv1.x + xv.z * wv2.x + xv.w * wv3.x;
            acc[i].y += xv.x * wv0.y + xv.y * wv1.y + xv.z * wv2.y + xv.w * wv3.y;
            acc[i].z += xv.x * wv0.z + xv.y * wv1.z + xv.z * wv2.z + xv.w * wv3.z;
            acc[i].w += xv.x * wv0.w + xv.y * wv1.w + xv.z * wv2.w + xv.w * wv3.w;
        }
    }
    // epilogue: cols 4cg..4cg+3 = head (cg>>4), feature pairs (cg&15)*2 +{0,1}
    {
        int hd = cg >> 4, pb = (cg & 15) * 2;
#pragma unroll
        for (int i = 0; i < 8; i++) {
            int n = nb + rg * 8 + i;
            if (n < NN) {
                __half2 lo = __floats2half2_rn(acc[i].x, acc[i].y);
                __half2 hi = __floats2half2_rn(acc[i].z, acc[i].w);
                uint2 pk = make_uint2(*(unsigned*)&lo, *(unsigned*)&hi);
                *((uint2*)&g_hh[n * 128 + hd * 32 + pb]) = pk;
            }
        }
    }
    // fused scores: thread t -> (row r, output o); e = x_row . wt[:,o]  (exact fp32)
    {
        int r = t >> 3, o = t & 7;
        float e = 0.f;
#pragma unroll 4
        for (int k4 = 0; k4 < IN / 4; k4++) {
            float4 xv = xs[r * (IN / 4) + k4];
            e += xv.x * ws[(4 * k4 + 0) * 8 + o] + xv.y * ws[(4 * k4 + 1) * 8 + o]
               + xv.z * ws[(4 * k4 + 2) * 8 + o] + xv.w * ws[(4 * k4 + 3) * 8 + o];
        }
        int n = nb + r;
        if (n < NN) {
            if (o & 1) ((float*)g_ed4)[n * 4 + (o >> 1)] = e;
            else       ((float*)g_es4)[n * 4 + (o >> 1)] = e;
        }
    }
}
__global__ void k_gemm1(const float* __restrict__ x, const float* __restrict__ W) {
    gemm_body<128>(x, W, 0);
}
__global__ void k_gemm2(const float* __restrict__ W) {
    gemm_body<64>(g_x2, W, 1024);
}

// ---------------- single-pass fused GAT: one warp per dst node -------------
// unshifted softmax (logits are O(1); identical after normalization)
__global__ void k_gat(const float* __restrict__ b, int statsOff) {
    int t = threadIdx.x, w = t >> 5, l = t & 31;
    int v = blockIdx.x * 16 + w;
    float p0 = 0.f, p1 = 0.f;
    if (v < NN) {
        int beg = g_row[v], end = g_row[v + 1];
        float4 ed = g_ed4[v];
        float s0 = 0.f, s1 = 0.f, s2 = 0.f, s3 = 0.f;
        float2 a0 = {0.f, 0.f}, a1 = {0.f, 0.f}, a2 = {0.f, 0.f}, a3 = {0.f, 0.f};
#pragma unroll 2
        for (int i = beg; i < end; i++) {
            int s = g_csrc[i];                       // broadcast
            float4 es = g_es4[s];                    // broadcast
            float e0 = es.x + ed.x; e0 = e0 > 0.f ? e0 : NEG * e0;
            float e1 = es.y + ed.y; e1 = e1 > 0.f ? e1 : NEG * e1;
            float e2 = es.z + ed.z; e2 = e2 > 0.f ? e2 : NEG * e2;
            float e3 = es.w + ed.w; e3 = e3 > 0.f ? e3 : NEG * e3;
            float q0 = __expf(e0), q1 = __expf(e1);
            float q2 = __expf(e2), q3 = __expf(e3);
            s0 += q0; s1 += q1; s2 += q2; s3 += q3;
            const __half2* hp = &g_hh[s * 128 + l];
            float2 f0 = __half22float2(hp[0]);
            float2 f1 = __half22float2(hp[32]);
            float2 f2 = __half22float2(hp[64]);
            float2 f3 = __half22float2(hp[96]);
            a0.x += f0.x * q0; a0.y += f0.y * q0;
            a1.x += f1.x * q1; a1.y += f1.y * q1;
            a2.x += f2.x * q2; a2.y += f2.y * q2;
            a3.x += f3.x * q3; a3.y += f3.y * q3;
        }
        float i0 = 0.25f / s0, i1 = 0.25f / s1;
        float i2 = 0.25f / s2, i3 = 0.25f / s3;
        p0 = a0.x * i0 + a1.x * i1 + a2.x * i2 + a3.x * i3 + b[2 * l];
        p1 = a0.y * i0 + a1.y * i1 + a2.y * i2 + a3.y * i3 + b[2 * l + 1];
        ((float2*)g_pre)[v * 32 + l] = make_float2(p0, p1);
    }
    // GraphNorm stats: block-reduce over 16 warps, 128 atomics per block
    __shared__ float ss0[512], sq0[512], ss1[512], sq1[512];
    ss0[t] = p0; sq0[t] = p0 * p0; ss1[t] = p1; sq1[t] = p1 * p1;
    __syncthreads();
    if (t < 64) {
        int lane = t >> 1, sel = t & 1;
        const float* sv = sel ? ss1 : ss0;
        const float* qv = sel ? sq1 : sq0;
        float a = 0.f, q = 0.f;
#pragma unroll
        for (int ww = 0; ww < 16; ww++) { a += sv[ww * 32 + lane]; q += qv[ww * 32 + lane]; }
        atomicAdd(&g_stats[statsOff + t], a);        // feature t = 2*lane + sel
        atomicAdd(&g_stats[statsOff + 64 + t], q);
    }
}

// GraphNorm affine + ReLU, stats derived inline
__global__ void k_norm(const float* __restrict__ w, const float* __restrict__ bb,
                       const float* __restrict__ gs, int statsOff) {
    int i = blockIdx.x * blockDim.x + threadIdx.x;
    if (i >= NN * HID) return;
    int c = i & 63;
    float mu = g_stats[statsOff + c] * (1.f / NN);
    float m2 = g_stats[statsOff + 64 + c] * (1.f / NN);
    float sc = gs[c];
    float var = m2 - 2.f * sc * mu * mu + sc * sc * mu * mu;
    float v = (g_pre[i] - mu * sc) * rsqrtf(var + EPSN) * w[c] + bb[c];
    g_x2[i] = v > 0.f ? v : 0.f;
}

// one warp per triplet: gather 4x64, layernorm(256), dot with fc_w
__global__ void k_trip(const int* __restrict__ trip, const float* __restrict__ lw,
                       const float* __restrict__ lb, const float* __restrict__ fw,
                       const float* __restrict__ fb, float* __restrict__ out) {
    int warp = (blockIdx.x * blockDim.x + threadIdx.x) >> 5;
    int l = threadIdx.x & 31;
    if (warp >= NT) return;
    int nodes[4];
#pragma unroll
    for (int q = 0; q < 4; q++) nodes[q] = trip[warp * 4 + q];
    float v[8];
    float sum = 0.f, ssq = 0.f;
#pragma unroll
    for (int j8 = 0; j8 < 8; j8++) {
        int j = j8 * 32 + l;
        v[j8] = g_x2[nodes[j8 >> 1] * HID + (j & 63)];
        sum += v[j8];
        ssq += v[j8] * v[j8];
    }
#pragma unroll
    for (int o = 16; o > 0; o >>= 1) {
        sum += __shfl_xor_sync(~0u, sum, o);
        ssq += __shfl_xor_sync(~0u, ssq, o);
    }
    float mu = sum * (1.f / 256.f);
    float var = ssq * (1.f / 256.f) - mu * mu;
    float inv = rsqrtf(var + EPSN);
    float res = 0.f;
#pragma unroll
    for (int j8 = 0; j8 < 8; j8++) {
        int j = j8 * 32 + l;
        res += ((v[j8] - mu) * inv * lw[j] + lb[j]) * fw[j];
    }
#pragma unroll
    for (int o = 16; o > 0; o >>= 1) res += __shfl_xor_sync(~0u, res, o);
    if (l == 0) out[warp] = res + fb[0];
}

// ---------------- host ----------------------------------------------------
extern "C" void kernel_launch(void* const* d_in, const int* in_sizes, int n_in,
                              void* d_out, int out_size) {
    const float* x   = (const float*)d_in[0];
    // d_in[1] = edge_weight : unused by the reference computation
    const float* W1  = (const float*)d_in[2];
    const float* as1 = (const float*)d_in[3];
    const float* ad1 = (const float*)d_in[4];
    const float* b1  = (const float*)d_in[5];
    const float* W2  = (const float*)d_in[6];
    const float* as2 = (const float*)d_in[7];
    const float* ad2 = (const float*)d_in[8];
    const float* b2  = (const float*)d_in[9];
    const float* g1w = (const float*)d_in[10];
    const float* g1b = (const float*)d_in[11];
    const float* g1s = (const float*)d_in[12];
    const float* g2w = (const float*)d_in[13];
    const float* g2b = (const float*)d_in[14];
    const float* g2s = (const float*)d_in[15];
    const float* lnw = (const float*)d_in[16];
    const float* lnb = (const float*)d_in[17];
    const float* fcw = (const float*)d_in[18];
    const float* fcb = (const float*)d_in[19];
    const int*   ei  = (const int*)d_in[20];
    const int*   trp = (const int*)d_in[21];
    float* out = (float*)d_out;

    // ---- CSR build + attention-vector projections ----
    k_rz<<<128, 256>>>();
    k_wt<<<128, 256>>>(W1, as1, ad1, 128, 0);
    k_wt<<<64, 256>>>(W2, as2, ad2, 64, 1024);
    k_hist<<<(NET + 255) / 256, 256>>>(ei);
    k_scan1<<<SCAN_BLKS, SCAN_CHUNK>>>();
    k_scan2<<<1, 32>>>();
    k_scan3<<<SCAN_BLKS, SCAN_CHUNK>>>();
    k_scatter<<<(NET + 255) / 256, 256>>>(ei);

    // ---- layer 1 ----
    k_gemm1<<<(NN + 31) / 32, 256>>>(x, W1);
    k_gat<<<(NN + 15) / 16, 512>>>(b1, 0);
    k_norm<<<(NN * HID + 255) / 256, 256>>>(g1w, g1b, g1s, 0);

    // ---- layer 2 ----
    k_gemm2<<<(NN + 31) / 32, 256>>>(W2);
    k_gat<<<(NN + 15) / 16, 512>>>(b2, 128);
    k_norm<<<(NN * HID + 255) / 256, 256>>>(g2w, g2b, g2s, 128);

    // ---- triplet head ----
    k_trip<<<(NT * 32 + 255) / 256, 256>>>(trp, lnw, lnb, fcw, fcb, out);
}